// round 1
// baseline (speedup 1.0000x reference)
#include <cuda_runtime.h>
#include <cuda_bf16.h>
#include <cstdint>

// Problem constants
#define BB 16
#define CIN 3
#define HH 256
#define WW 256
#define COUT 64
#define KK9 9
#define NPIX (BB*HH*WW)          // 1048576 per channel
#define PLANE (HH*WW)            // 65536

// Scratch for BN statistics (device globals: no allocation allowed)
__device__ float g_psum[COUT*BB];
__device__ float g_psq[COUT*BB];
__device__ float g_scale[COUT];
__device__ float g_shift[COUT];

// ---------------------------------------------------------------------------
// Kernel A: fused offset-conv + deformable sampling + (res conv + dcn) GEMM
// One block = one (b,h) row of 256 pixels. Writes y into out (scratch).
// ---------------------------------------------------------------------------
__global__ __launch_bounds__(256, 2)
void fused_main(const float* __restrict__ x,
                const float* __restrict__ w_off,
                const float* __restrict__ b_off,
                const float* __restrict__ w_dcn,
                const float* __restrict__ w_conv,
                const float* __restrict__ b_conv,
                float* __restrict__ out)
{
    __shared__ float s_wcomb[COUT][56];   // [c][0..26]=w_conv, [27..53]=w_dcn, pad 2
    __shared__ float s_woff[18][28];      // offset conv weights, padded rows
    __shared__ float s_x[3][3][260];      // 3 channels x 3 rows x (256+2 halo), padded
    __shared__ float s_bconv[COUT];
    __shared__ float s_boff[18];

    const int tid = threadIdx.x;
    const int bidx = blockIdx.x;
    const int b = bidx >> 8;
    const int h = bidx & 255;

    // --- stage weights ---
    for (int i = tid; i < COUT*56; i += 256) {
        int c = i / 56, j = i % 56;
        float v;
        if (j < 27)       v = w_conv[c*27 + j];
        else if (j < 54)  v = w_dcn[c*27 + (j-27)];
        else              v = 0.f;
        s_wcomb[c][j] = v;
    }
    for (int i = tid; i < 18*28; i += 256) {
        int o = i / 28, j = i % 28;
        s_woff[o][j] = (j < 27) ? w_off[o*27 + j] : 0.f;
    }
    if (tid < COUT) s_bconv[tid] = b_conv[tid];
    if (tid < 18)   s_boff[tid]  = b_off[tid];

    // --- stage x rows h-1..h+1 with 1-col halo, zero padded ---
    for (int i = tid; i < 3*3*258; i += 256) {
        int ci = i / (3*258);
        int r  = (i / 258) % 3;
        int cc = i % 258;
        int gy = h - 1 + r;
        int gx = cc - 1;
        float v = 0.f;
        if (gy >= 0 && gy < HH && gx >= 0 && gx < WW)
            v = x[((size_t)(b*3 + ci)*HH + gy)*WW + gx];
        s_x[ci][r][cc] = v;
    }
    __syncthreads();

    const int w = tid;

    // fv[0..26]  = im2col taps (zero padded), order ci*9 + ky*3 + kx
    // fv[27..53] = deformable bilinear samples, order 27 + ci*9 + k
    float fv[56];

    #pragma unroll
    for (int ci = 0; ci < 3; ci++)
        #pragma unroll
        for (int k = 0; k < 9; k++)
            fv[ci*9 + k] = s_x[ci][k/3][w + (k%3)];

    // --- per-tap: offset conv (dy,dx) then bilinear sample of 3 channels ---
    const float* xb = x + (size_t)b * 3 * PLANE;
    #pragma unroll
    for (int k = 0; k < 9; k++) {
        float dy = s_boff[2*k];
        float dx = s_boff[2*k + 1];
        #pragma unroll
        for (int j = 0; j < 27; j++) {
            dy = fmaf(s_woff[2*k][j],   fv[j], dy);
            dx = fmaf(s_woff[2*k+1][j], fv[j], dx);
        }
        float py = (float)(h + k/3 - 1) + dy;
        float px = (float)(w + k%3 - 1) + dx;
        float y0 = floorf(py), x0 = floorf(px);
        float ly = py - y0,    lx = px - x0;
        float hy = 1.f - ly,   hx = 1.f - lx;
        float y1 = y0 + 1.f,   x1 = x0 + 1.f;
        bool vy0 = (y0 >= 0.f) && (y0 <= 255.f);
        bool vy1 = (y1 >= 0.f) && (y1 <= 255.f);
        bool vx0 = (x0 >= 0.f) && (x0 <= 255.f);
        bool vx1 = (x1 >= 0.f) && (x1 <= 255.f);
        float w00 = hy*hx * ((vy0 && vx0) ? 1.f : 0.f);
        float w01 = hy*lx * ((vy0 && vx1) ? 1.f : 0.f);
        float w10 = ly*hx * ((vy1 && vx0) ? 1.f : 0.f);
        float w11 = ly*lx * ((vy1 && vx1) ? 1.f : 0.f);
        int iy0 = min(max((int)y0, 0), 255);
        int iy1 = min(max((int)y1, 0), 255);
        int ix0 = min(max((int)x0, 0), 255);
        int ix1 = min(max((int)x1, 0), 255);
        int i00 = iy0*WW + ix0, i01 = iy0*WW + ix1;
        int i10 = iy1*WW + ix0, i11 = iy1*WW + ix1;
        #pragma unroll
        for (int ci = 0; ci < 3; ci++) {
            const float* xc = xb + ci * PLANE;
            float v = w00 * __ldg(xc + i00) + w01 * __ldg(xc + i01)
                    + w10 * __ldg(xc + i10) + w11 * __ldg(xc + i11);
            fv[27 + ci*9 + k] = v;
        }
    }
    fv[54] = 0.f;
    fv[55] = 0.f;

    // --- pack into f32x2 operands ---
    unsigned long long vp[28];
    #pragma unroll
    for (int p = 0; p < 28; p++) {
        vp[p] = (unsigned long long)__float_as_uint(fv[2*p])
              | ((unsigned long long)__float_as_uint(fv[2*p+1]) << 32);
    }

    // --- 64-channel fused GEMM: 28 packed FFMA2 per channel ---
    float* outp = out + (size_t)b * COUT * PLANE + (size_t)h * WW + w;
    for (int c = 0; c < COUT; c++) {
        const ulonglong2* wp = reinterpret_cast<const ulonglong2*>(&s_wcomb[c][0]);
        unsigned long long a0 = 0ULL, a1 = 0ULL;
        #pragma unroll
        for (int q = 0; q < 14; q++) {
            ulonglong2 ww = wp[q];
            asm("fma.rn.f32x2 %0, %1, %2, %0;" : "+l"(a0) : "l"(ww.x), "l"(vp[2*q]));
            asm("fma.rn.f32x2 %0, %1, %2, %0;" : "+l"(a1) : "l"(ww.y), "l"(vp[2*q+1]));
        }
        float r0 = __uint_as_float((unsigned)(a0 & 0xffffffffULL));
        float r1 = __uint_as_float((unsigned)(a0 >> 32));
        float r2 = __uint_as_float((unsigned)(a1 & 0xffffffffULL));
        float r3 = __uint_as_float((unsigned)(a1 >> 32));
        float res = s_bconv[c] + ((r0 + r1) + (r2 + r3));
        outp[(size_t)c << 16] = res;
    }
}

// ---------------------------------------------------------------------------
// Kernel B: per-(channel,batch) partial sums (deterministic, no atomics)
// ---------------------------------------------------------------------------
__global__ __launch_bounds__(256)
void reduce_kernel(const float* __restrict__ y)
{
    const int bc = blockIdx.x;            // c*16 + b
    const int c = bc >> 4, b = bc & 15;
    const float4* p = reinterpret_cast<const float4*>(y + ((size_t)b*COUT + c) * PLANE);
    const int tid = threadIdx.x;
    float s = 0.f, q = 0.f;
    #pragma unroll 4
    for (int i = tid; i < PLANE/4; i += 256) {
        float4 v = p[i];
        s += (v.x + v.y) + (v.z + v.w);
        q += (v.x*v.x + v.y*v.y) + (v.z*v.z + v.w*v.w);
    }
    __shared__ float ss[256], sq[256];
    ss[tid] = s; sq[tid] = q;
    __syncthreads();
    for (int st = 128; st > 0; st >>= 1) {
        if (tid < st) { ss[tid] += ss[tid+st]; sq[tid] += sq[tid+st]; }
        __syncthreads();
    }
    if (tid == 0) { g_psum[bc] = ss[0]; g_psq[bc] = sq[0]; }
}

// ---------------------------------------------------------------------------
// Kernel C: finalize mean/var -> scale/shift
// ---------------------------------------------------------------------------
__global__ void stats_kernel(const float* __restrict__ gamma,
                             const float* __restrict__ beta)
{
    const int c = threadIdx.x;
    if (c >= COUT) return;
    float s = 0.f, q = 0.f;
    #pragma unroll
    for (int b = 0; b < 16; b++) { s += g_psum[c*16 + b]; q += g_psq[c*16 + b]; }
    const float invN = 1.f / (float)NPIX;
    float mean = s * invN;
    float var  = q * invN - mean * mean;
    float inv  = rsqrtf(var + 1e-5f);
    float sc   = gamma[c] * inv;
    g_scale[c] = sc;
    g_shift[c] = beta[c] - mean * sc;
}

// ---------------------------------------------------------------------------
// Kernel D: in-place normalize + SiLU
// ---------------------------------------------------------------------------
__global__ __launch_bounds__(256)
void norm_silu(float* __restrict__ y)
{
    const int idx = blockIdx.x * 256 + threadIdx.x;   // float4 index
    const int c = (idx >> 14) & 63;                   // 16384 float4 per plane
    const float sc = g_scale[c];
    const float sh = g_shift[c];
    float4 v = reinterpret_cast<const float4*>(y)[idx];
    float t0 = fmaf(v.x, sc, sh);
    float t1 = fmaf(v.y, sc, sh);
    float t2 = fmaf(v.z, sc, sh);
    float t3 = fmaf(v.w, sc, sh);
    v.x = t0 / (1.f + __expf(-t0));
    v.y = t1 / (1.f + __expf(-t1));
    v.z = t2 / (1.f + __expf(-t2));
    v.w = t3 / (1.f + __expf(-t3));
    reinterpret_cast<float4*>(y)[idx] = v;
}

// ---------------------------------------------------------------------------
extern "C" void kernel_launch(void* const* d_in, const int* in_sizes, int n_in,
                              void* d_out, int out_size)
{
    const float* x      = (const float*)d_in[0];
    const float* w_off  = (const float*)d_in[1];
    const float* b_off  = (const float*)d_in[2];
    const float* w_dcn  = (const float*)d_in[3];
    const float* w_conv = (const float*)d_in[4];
    const float* b_conv = (const float*)d_in[5];
    const float* gamma  = (const float*)d_in[6];
    const float* beta   = (const float*)d_in[7];
    float* out = (float*)d_out;

    fused_main<<<BB*HH, 256>>>(x, w_off, b_off, w_dcn, w_conv, b_conv, out);
    reduce_kernel<<<COUT*BB, 256>>>(out);
    stats_kernel<<<1, 64>>>(gamma, beta);
    norm_silu<<<(BB*COUT*PLANE)/4/256, 256>>>(out);
}

// round 2
// speedup vs baseline: 1.0508x; 1.0508x over previous
#include <cuda_runtime.h>
#include <cuda_bf16.h>
#include <cstdint>

#define BB 16
#define CIN 3
#define HH 256
#define WW 256
#define COUT 64
#define NPIX (BB*HH*WW)
#define PLANE (HH*WW)
#define KTOT 54
#define NBLK (BB*HH)              // 4096 row-blocks

typedef unsigned long long ull;

// BN partial sums: [channel][block]
__device__ float g_partS[COUT * NBLK];
__device__ float g_partQ[COUT * NBLK];
__device__ float g_scale[COUT];
__device__ float g_shift[COUT];

// ---- dynamic SMEM layout (bytes, 16B aligned) ----
#define OFF_WDUP 0                        // float2[54][64]      27648
#define OFF_BDUP (OFF_WDUP + 54*64*8)     // float2[64]            512
#define OFF_TAPS (OFF_BDUP + 64*8)        // float[54][256]      55296
#define OFF_X    (OFF_TAPS + 54*256*4)    // float[3][3][264]     9504  (overlaid by rs/rq later)
#define OFF_RS   OFF_X                    // float[64][17]        4352
#define OFF_RQ   (OFF_RS + 64*17*4)       // float[64][17]        4352
#define OFF_WOFF (OFF_X + 3*3*264*4)      // float[18][28]        2016
#define SMEM_BYTES (OFF_WOFF + 18*28*4)   // = 94976

__device__ __forceinline__ void fma2(ull& a, ull b, ull c) {
    asm("fma.rn.f32x2 %0, %1, %2, %0;" : "+l"(a) : "l"(b), "l"(c));
}
__device__ __forceinline__ ull add2(ull a, ull b) {
    ull r; asm("add.rn.f32x2 %0, %1, %2;" : "=l"(r) : "l"(a), "l"(b)); return r;
}
__device__ __forceinline__ float lo32(ull v) { return __uint_as_float((unsigned)v); }
__device__ __forceinline__ float hi32(ull v) { return __uint_as_float((unsigned)(v >> 32)); }

// ---------------------------------------------------------------------------
// Kernel A: offset-conv + deform sampling -> taps in SMEM -> register-blocked
// fused GEMM (conv+dcn) with f32x2, + fused BN partial reduction.
// One block = one (b,h) row of 256 pixels.
// ---------------------------------------------------------------------------
__global__ __launch_bounds__(256, 2)
void fused_main(const float* __restrict__ x,
                const float* __restrict__ w_off,
                const float* __restrict__ b_off,
                const float* __restrict__ w_dcn,
                const float* __restrict__ w_conv,
                const float* __restrict__ b_conv,
                float* __restrict__ out)
{
    extern __shared__ __align__(16) char smem[];
    float2* s_wdup = (float2*)(smem + OFF_WDUP);   // [k*64 + c] = (w,w)
    ull*    s_bdup = (ull*)   (smem + OFF_BDUP);   // (b,b)
    float*  s_taps = (float*) (smem + OFF_TAPS);   // [k*256 + p]
    float*  s_x    = (float*) (smem + OFF_X);      // [(ci*3+r)*264 + col]
    float*  s_rs   = (float*) (smem + OFF_RS);     // [c*17 + pg]
    float*  s_rq   = (float*) (smem + OFF_RQ);
    float*  s_woff = (float*) (smem + OFF_WOFF);   // [o*28 + j]
    __shared__ float s_boff[18];

    const int tid  = threadIdx.x;
    const int bidx = blockIdx.x;
    const int b    = bidx >> 8;
    const int h    = bidx & 255;

    // ---- stage weights (duplicated pairs) ----
    for (int i = tid; i < KTOT*COUT; i += 256) {
        int k = i >> 6, c = i & 63;
        float v = (k < 27) ? w_conv[c*27 + k] : w_dcn[c*27 + (k - 27)];
        s_wdup[i] = make_float2(v, v);
    }
    for (int i = tid; i < 18*28; i += 256) {
        int o = i / 28, j = i % 28;
        s_woff[i] = (j < 27) ? w_off[o*27 + j] : 0.f;
    }
    if (tid < COUT) {
        float bv = b_conv[tid];
        ull p = (ull)__float_as_uint(bv) | ((ull)__float_as_uint(bv) << 32);
        s_bdup[tid] = p;
    }
    if (tid < 18) s_boff[tid] = b_off[tid];

    // ---- stage x rows h-1..h+1 with halo ----
    for (int i = tid; i < 3*3*258; i += 256) {
        int ci = i / (3*258);
        int r  = (i / 258) % 3;
        int cc = i % 258;
        int gy = h - 1 + r;
        int gx = cc - 1;
        float v = 0.f;
        if (gy >= 0 && gy < HH && gx >= 0 && gx < WW)
            v = x[((size_t)(b*3 + ci)*HH + gy)*WW + gx];
        s_x[(ci*3 + r)*264 + cc] = v;
    }
    __syncthreads();

    // ================= Phase 1: build taps for pixel w = tid =================
    {
        const int w = tid;
        float fv[KTOT];

        #pragma unroll
        for (int ci = 0; ci < 3; ci++)
            #pragma unroll
            for (int k = 0; k < 9; k++)
                fv[ci*9 + k] = s_x[(ci*3 + k/3)*264 + w + (k%3)];

        const float* xb = x + (size_t)b * 3 * PLANE;
        #pragma unroll
        for (int k = 0; k < 9; k++) {
            float dy = s_boff[2*k];
            float dx = s_boff[2*k + 1];
            #pragma unroll
            for (int j = 0; j < 27; j++) {
                dy = fmaf(s_woff[(2*k)*28 + j],   fv[j], dy);
                dx = fmaf(s_woff[(2*k+1)*28 + j], fv[j], dx);
            }
            float py = (float)(h + k/3 - 1) + dy;
            float px = (float)(w + k%3 - 1) + dx;
            float y0 = floorf(py), x0 = floorf(px);
            float ly = py - y0,    lx = px - x0;
            float hy = 1.f - ly,   hx = 1.f - lx;
            float y1 = y0 + 1.f,   x1 = x0 + 1.f;
            bool vy0 = (y0 >= 0.f) && (y0 <= 255.f);
            bool vy1 = (y1 >= 0.f) && (y1 <= 255.f);
            bool vx0 = (x0 >= 0.f) && (x0 <= 255.f);
            bool vx1 = (x1 >= 0.f) && (x1 <= 255.f);
            float w00 = hy*hx * ((vy0 && vx0) ? 1.f : 0.f);
            float w01 = hy*lx * ((vy0 && vx1) ? 1.f : 0.f);
            float w10 = ly*hx * ((vy1 && vx0) ? 1.f : 0.f);
            float w11 = ly*lx * ((vy1 && vx1) ? 1.f : 0.f);
            int iy0 = min(max((int)y0, 0), 255);
            int iy1 = min(max((int)y1, 0), 255);
            int ix0 = min(max((int)x0, 0), 255);
            int ix1 = min(max((int)x1, 0), 255);
            int i00 = iy0*WW + ix0, i01 = iy0*WW + ix1;
            int i10 = iy1*WW + ix0, i11 = iy1*WW + ix1;
            #pragma unroll
            for (int ci = 0; ci < 3; ci++) {
                const float* xc = xb + ci * PLANE;
                fv[27 + ci*9 + k] = w00 * __ldg(xc + i00) + w01 * __ldg(xc + i01)
                                  + w10 * __ldg(xc + i10) + w11 * __ldg(xc + i11);
            }
        }
        #pragma unroll
        for (int k = 0; k < KTOT; k++)
            s_taps[(k << 8) + w] = fv[k];
    }
    __syncthreads();

    // ========== Phase 2: 4 channels x 16 pixels per thread, f32x2 ==========
    const int cg    = tid & 15;     // channel group: channels 4cg..4cg+3
    const int pg    = tid >> 4;     // pixel group:   pixels 16pg..16pg+15
    const int pbase = pg << 4;

    ull acc[4][8];
    #pragma unroll
    for (int c = 0; c < 4; c++)
        #pragma unroll
        for (int p = 0; p < 8; p++) acc[c][p] = 0ULL;

    #pragma unroll 2
    for (int k = 0; k < KTOT; k++) {
        const ulonglong2* wp = reinterpret_cast<const ulonglong2*>(s_wdup + (k << 6) + (cg << 2));
        ulonglong2 wA = wp[0];
        ulonglong2 wB = wp[1];
        const ulonglong2* tp = reinterpret_cast<const ulonglong2*>(s_taps + (k << 8) + pbase);
        ulonglong2 tA = tp[0], tB = tp[1], tC = tp[2], tD = tp[3];
        ull wv[4] = {wA.x, wA.y, wB.x, wB.y};
        ull tv[8] = {tA.x, tA.y, tB.x, tB.y, tC.x, tC.y, tD.x, tD.y};
        #pragma unroll
        for (int c = 0; c < 4; c++)
            #pragma unroll
            for (int p = 0; p < 8; p++)
                fma2(acc[c][p], wv[c], tv[p]);
    }

    // ---- epilogue: bias, store, BN partials ----
    float* outrow = out + (size_t)b * COUT * PLANE + (size_t)h * WW + pbase;
    #pragma unroll
    for (int c = 0; c < 4; c++) {
        const int C = (cg << 2) + c;
        const ull bias2 = s_bdup[C];
        ull v[8];
        #pragma unroll
        for (int p = 0; p < 8; p++) v[p] = add2(acc[c][p], bias2);

        ulonglong2* op = reinterpret_cast<ulonglong2*>(outrow + ((size_t)C << 16));
        op[0] = make_ulonglong2(v[0], v[1]);
        op[1] = make_ulonglong2(v[2], v[3]);
        op[2] = make_ulonglong2(v[4], v[5]);
        op[3] = make_ulonglong2(v[6], v[7]);

        // sum / sumsq over the 16 pixels
        ull s01 = add2(v[0], v[1]), s23 = add2(v[2], v[3]);
        ull s45 = add2(v[4], v[5]), s67 = add2(v[6], v[7]);
        ull S = add2(add2(s01, s23), add2(s45, s67));
        ull Q = 0ULL;
        #pragma unroll
        for (int p = 0; p < 8; p++) fma2(Q, v[p], v[p]);
        s_rs[C*17 + pg] = lo32(S) + hi32(S);
        s_rq[C*17 + pg] = lo32(Q) + hi32(Q);
    }
    __syncthreads();

    if (tid < COUT) {
        float s = 0.f, q = 0.f;
        #pragma unroll
        for (int p = 0; p < 16; p++) { s += s_rs[tid*17 + p]; q += s_rq[tid*17 + p]; }
        g_partS[tid*NBLK + bidx] = s;
        g_partQ[tid*NBLK + bidx] = q;
    }
}

// ---------------------------------------------------------------------------
// Kernel B: per-channel stats finalize (one block per channel)
// ---------------------------------------------------------------------------
__global__ __launch_bounds__(256)
void stats_kernel(const float* __restrict__ gamma,
                  const float* __restrict__ beta)
{
    const int c = blockIdx.x;
    const int tid = threadIdx.x;
    float s = 0.f, q = 0.f;
    for (int i = tid; i < NBLK; i += 256) {
        s += g_partS[c*NBLK + i];
        q += g_partQ[c*NBLK + i];
    }
    __shared__ float ss[256], sq[256];
    ss[tid] = s; sq[tid] = q;
    __syncthreads();
    for (int st = 128; st > 0; st >>= 1) {
        if (tid < st) { ss[tid] += ss[tid+st]; sq[tid] += sq[tid+st]; }
        __syncthreads();
    }
    if (tid == 0) {
        const float invN = 1.f / (float)NPIX;
        float mean = ss[0] * invN;
        float var  = sq[0] * invN - mean * mean;
        float inv  = rsqrtf(var + 1e-5f);
        float sc   = gamma[c] * inv;
        g_scale[c] = sc;
        g_shift[c] = beta[c] - mean * sc;
    }
}

// ---------------------------------------------------------------------------
// Kernel C: in-place normalize + SiLU (2 float4 per thread)
// ---------------------------------------------------------------------------
#define N4TOT ((size_t)BB*COUT*PLANE/4)   // 16777216
#define N4HALF (N4TOT/2)                  // 8388608

__global__ __launch_bounds__(256)
void norm_silu(float* __restrict__ y)
{
    const size_t i0 = (size_t)blockIdx.x * 256 + threadIdx.x;
    float4* yp = reinterpret_cast<float4*>(y);

    #pragma unroll
    for (int r = 0; r < 2; r++) {
        size_t idx = i0 + (size_t)r * N4HALF;
        int c = (int)((idx >> 14) & 63);
        float sc = g_scale[c];
        float sh = g_shift[c];
        float4 v = yp[idx];
        float t0 = fmaf(v.x, sc, sh);
        float t1 = fmaf(v.y, sc, sh);
        float t2 = fmaf(v.z, sc, sh);
        float t3 = fmaf(v.w, sc, sh);
        v.x = t0 / (1.f + __expf(-t0));
        v.y = t1 / (1.f + __expf(-t1));
        v.z = t2 / (1.f + __expf(-t2));
        v.w = t3 / (1.f + __expf(-t3));
        yp[idx] = v;
    }
}

// ---------------------------------------------------------------------------
extern "C" void kernel_launch(void* const* d_in, const int* in_sizes, int n_in,
                              void* d_out, int out_size)
{
    const float* x      = (const float*)d_in[0];
    const float* w_off  = (const float*)d_in[1];
    const float* b_off  = (const float*)d_in[2];
    const float* w_dcn  = (const float*)d_in[3];
    const float* w_conv = (const float*)d_in[4];
    const float* b_conv = (const float*)d_in[5];
    const float* gamma  = (const float*)d_in[6];
    const float* beta   = (const float*)d_in[7];
    float* out = (float*)d_out;

    cudaFuncSetAttribute(fused_main, cudaFuncAttributeMaxDynamicSharedMemorySize, SMEM_BYTES);

    fused_main<<<NBLK, 256, SMEM_BYTES>>>(x, w_off, b_off, w_dcn, w_conv, b_conv, out);
    stats_kernel<<<COUT, 256>>>(gamma, beta);
    norm_silu<<<N4HALF/256, 256>>>(out);
}

// round 3
// speedup vs baseline: 1.0913x; 1.0385x over previous
#include <cuda_runtime.h>
#include <cuda_bf16.h>
#include <cstdint>

#define BB 16
#define CIN 3
#define HH 256
#define WW 256
#define COUT 64
#define NPIX (BB*HH*WW)
#define PLANE (HH*WW)
#define KTOT 54
#define NBLK (BB*HH)              // 4096 row-blocks

typedef unsigned long long ull;

// BN partial sums: [channel][block]
__device__ float g_partS[COUT * NBLK];
__device__ float g_partQ[COUT * NBLK];
__device__ float g_scale[COUT];
__device__ float g_shift[COUT];

// ---- dynamic SMEM layout (bytes, 16B aligned) ----
#define OFF_W    0                        // float[54][64]       13824 (scalar weights)
#define OFF_BDUP (OFF_W + 54*64*4)        // ull[64]               512
#define OFF_TAPS (OFF_BDUP + 64*8)        // float[54][256]      55296 (overlaid by rs/rq in epilogue)
#define OFF_RS   OFF_TAPS                 // float[64][33]        8448
#define OFF_RQ   (OFF_RS + 64*33*4)       // float[64][33]        8448
#define OFF_X    (OFF_TAPS + 54*256*4)    // float[3][3][264]     9504
#define OFF_WOFF (OFF_X + 3*3*264*4)      // float[18][28]        2016
#define SMEM_BYTES (OFF_WOFF + 18*28*4)   // = 81152

__device__ __forceinline__ void fma2(ull& a, ull b, ull c) {
    asm("fma.rn.f32x2 %0, %1, %2, %0;" : "+l"(a) : "l"(b), "l"(c));
}
__device__ __forceinline__ ull add2(ull a, ull b) {
    ull r; asm("add.rn.f32x2 %0, %1, %2;" : "=l"(r) : "l"(a), "l"(b)); return r;
}
__device__ __forceinline__ ull dup2(float w) {
    ull r; asm("mov.b64 %0, {%1, %1};" : "=l"(r) : "r"(__float_as_uint(w))); return r;
}
__device__ __forceinline__ float lo32(ull v) { return __uint_as_float((unsigned)v); }
__device__ __forceinline__ float hi32(ull v) { return __uint_as_float((unsigned)(v >> 32)); }

// ---------------------------------------------------------------------------
// Kernel A: offset-conv + deform sampling -> taps in SMEM -> register-blocked
// fused GEMM (8 ch x 8 px per thread, f32x2), + fused BN partial reduction.
// One block = one (b,h) row of 256 pixels.
// ---------------------------------------------------------------------------
__global__ __launch_bounds__(256, 2)
void fused_main(const float* __restrict__ x,
                const float* __restrict__ w_off,
                const float* __restrict__ b_off,
                const float* __restrict__ w_dcn,
                const float* __restrict__ w_conv,
                const float* __restrict__ b_conv,
                float* __restrict__ out)
{
    extern __shared__ __align__(16) char smem[];
    float* s_w    = (float*)(smem + OFF_W);      // [k*64 + c]
    ull*   s_bdup = (ull*)  (smem + OFF_BDUP);
    float* s_taps = (float*)(smem + OFF_TAPS);   // [k*256 + p]
    float* s_rs   = (float*)(smem + OFF_RS);     // [c*33 + pg]
    float* s_rq   = (float*)(smem + OFF_RQ);
    float* s_x    = (float*)(smem + OFF_X);      // [(ci*3+r)*264 + col]
    float* s_woff = (float*)(smem + OFF_WOFF);   // [o*28 + j]
    __shared__ float s_boff[18];

    const int tid  = threadIdx.x;
    const int bidx = blockIdx.x;
    const int b    = bidx >> 8;
    const int h    = bidx & 255;

    // ---- stage weights (scalar) ----
    for (int i = tid; i < KTOT*COUT; i += 256) {
        int k = i >> 6, c = i & 63;
        s_w[i] = (k < 27) ? w_conv[c*27 + k] : w_dcn[c*27 + (k - 27)];
    }
    for (int i = tid; i < 18*28; i += 256) {
        int o = i / 28, j = i % 28;
        s_woff[i] = (j < 27) ? w_off[o*27 + j] : 0.f;
    }
    if (tid < COUT) {
        float bv = b_conv[tid];
        s_bdup[tid] = (ull)__float_as_uint(bv) | ((ull)__float_as_uint(bv) << 32);
    }
    if (tid < 18) s_boff[tid] = b_off[tid];

    // ---- stage x rows h-1..h+1 with halo ----
    for (int i = tid; i < 3*3*258; i += 256) {
        int ci = i / (3*258);
        int r  = (i / 258) % 3;
        int cc = i % 258;
        int gy = h - 1 + r;
        int gx = cc - 1;
        float v = 0.f;
        if (gy >= 0 && gy < HH && gx >= 0 && gx < WW)
            v = x[((size_t)(b*3 + ci)*HH + gy)*WW + gx];
        s_x[(ci*3 + r)*264 + cc] = v;
    }
    __syncthreads();

    // ================= Phase 1: build taps for pixel w = tid =================
    {
        const int w = tid;
        float fv[KTOT];

        #pragma unroll
        for (int ci = 0; ci < 3; ci++)
            #pragma unroll
            for (int k = 0; k < 9; k++)
                fv[ci*9 + k] = s_x[(ci*3 + k/3)*264 + w + (k%3)];

        const float* xb = x + (size_t)b * 3 * PLANE;
        #pragma unroll
        for (int k = 0; k < 9; k++) {
            float dy = s_boff[2*k];
            float dx = s_boff[2*k + 1];
            #pragma unroll
            for (int j = 0; j < 27; j++) {
                dy = fmaf(s_woff[(2*k)*28 + j],   fv[j], dy);
                dx = fmaf(s_woff[(2*k+1)*28 + j], fv[j], dx);
            }
            float py = (float)(h + k/3 - 1) + dy;
            float px = (float)(w + k%3 - 1) + dx;
            float y0 = floorf(py), x0 = floorf(px);
            float ly = py - y0,    lx = px - x0;
            float hy = 1.f - ly,   hx = 1.f - lx;
            float y1 = y0 + 1.f,   x1 = x0 + 1.f;
            bool vy0 = (y0 >= 0.f) && (y0 <= 255.f);
            bool vy1 = (y1 >= 0.f) && (y1 <= 255.f);
            bool vx0 = (x0 >= 0.f) && (x0 <= 255.f);
            bool vx1 = (x1 >= 0.f) && (x1 <= 255.f);
            float w00 = hy*hx * ((vy0 && vx0) ? 1.f : 0.f);
            float w01 = hy*lx * ((vy0 && vx1) ? 1.f : 0.f);
            float w10 = ly*hx * ((vy1 && vx0) ? 1.f : 0.f);
            float w11 = ly*lx * ((vy1 && vx1) ? 1.f : 0.f);
            int iy0 = min(max((int)y0, 0), 255);
            int iy1 = min(max((int)y1, 0), 255);
            int ix0 = min(max((int)x0, 0), 255);
            int ix1 = min(max((int)x1, 0), 255);
            int i00 = iy0*WW + ix0, i01 = iy0*WW + ix1;
            int i10 = iy1*WW + ix0, i11 = iy1*WW + ix1;
            #pragma unroll
            for (int ci = 0; ci < 3; ci++) {
                const float* xc = xb + ci * PLANE;
                fv[27 + ci*9 + k] = w00 * __ldg(xc + i00) + w01 * __ldg(xc + i01)
                                  + w10 * __ldg(xc + i10) + w11 * __ldg(xc + i11);
            }
        }
        #pragma unroll
        for (int k = 0; k < KTOT; k++)
            s_taps[(k << 8) + w] = fv[k];
    }
    __syncthreads();

    // ========== Phase 2: 8 channels x 8 pixels per thread, f32x2 ==========
    const int cg    = tid & 7;      // channel group: channels 8cg..8cg+7
    const int pg    = tid >> 3;     // pixel group:   pixels 8pg..8pg+7
    const int pbase = pg << 3;
    const int cbase = cg << 3;

    ull acc[8][4];
    #pragma unroll
    for (int c = 0; c < 8; c++)
        #pragma unroll
        for (int p = 0; p < 4; p++) acc[c][p] = 0ULL;

    #pragma unroll 2
    for (int k = 0; k < KTOT; k++) {
        const float4* wr = reinterpret_cast<const float4*>(s_w + (k << 6) + cbase);
        float4 w0 = wr[0], w1 = wr[1];
        const ulonglong2* tp = reinterpret_cast<const ulonglong2*>(s_taps + (k << 8) + pbase);
        ulonglong2 tA = tp[0], tB = tp[1];
        ull tv[4] = {tA.x, tA.y, tB.x, tB.y};
        float wv[8] = {w0.x, w0.y, w0.z, w0.w, w1.x, w1.y, w1.z, w1.w};
        #pragma unroll
        for (int c = 0; c < 8; c++) {
            ull wd = dup2(wv[c]);
            #pragma unroll
            for (int p = 0; p < 4; p++)
                fma2(acc[c][p], wd, tv[p]);
        }
    }
    __syncthreads();   // protect s_taps before rs/rq overlay

    // ---- epilogue: bias, store, BN partials ----
    float* outrow = out + (size_t)b * COUT * PLANE + (size_t)h * WW + pbase;
    #pragma unroll
    for (int c = 0; c < 8; c++) {
        const int C = cbase + c;
        const ull bias2 = s_bdup[C];
        ull v[4];
        #pragma unroll
        for (int p = 0; p < 4; p++) v[p] = add2(acc[c][p], bias2);

        ulonglong2* op = reinterpret_cast<ulonglong2*>(outrow + ((size_t)C << 16));
        op[0] = make_ulonglong2(v[0], v[1]);
        op[1] = make_ulonglong2(v[2], v[3]);

        ull S = add2(add2(v[0], v[1]), add2(v[2], v[3]));
        ull Q = 0ULL;
        #pragma unroll
        for (int p = 0; p < 4; p++) fma2(Q, v[p], v[p]);
        s_rs[C*33 + pg] = lo32(S) + hi32(S);
        s_rq[C*33 + pg] = lo32(Q) + hi32(Q);
    }
    __syncthreads();

    if (tid < COUT) {
        float s = 0.f, q = 0.f;
        #pragma unroll
        for (int p = 0; p < 32; p++) { s += s_rs[tid*33 + p]; q += s_rq[tid*33 + p]; }
        g_partS[tid*NBLK + bidx] = s;
        g_partQ[tid*NBLK + bidx] = q;
    }
}

// ---------------------------------------------------------------------------
// Kernel B: per-channel stats finalize (one block per channel)
// ---------------------------------------------------------------------------
__global__ __launch_bounds__(256)
void stats_kernel(const float* __restrict__ gamma,
                  const float* __restrict__ beta)
{
    const int c = blockIdx.x;
    const int tid = threadIdx.x;
    float s = 0.f, q = 0.f;
    for (int i = tid; i < NBLK; i += 256) {
        s += g_partS[c*NBLK + i];
        q += g_partQ[c*NBLK + i];
    }
    __shared__ float ss[256], sq[256];
    ss[tid] = s; sq[tid] = q;
    __syncthreads();
    for (int st = 128; st > 0; st >>= 1) {
        if (tid < st) { ss[tid] += ss[tid+st]; sq[tid] += sq[tid+st]; }
        __syncthreads();
    }
    if (tid == 0) {
        const float invN = 1.f / (float)NPIX;
        float mean = ss[0] * invN;
        float var  = sq[0] * invN - mean * mean;
        float inv  = rsqrtf(var + 1e-5f);
        float sc   = gamma[c] * inv;
        g_scale[c] = sc;
        g_shift[c] = beta[c] - mean * sc;
    }
}

// ---------------------------------------------------------------------------
// Kernel C: in-place normalize + SiLU (2 float4 per thread)
// ---------------------------------------------------------------------------
#define N4TOT ((size_t)BB*COUT*PLANE/4)   // 16777216
#define N4HALF (N4TOT/2)                  // 8388608

__global__ __launch_bounds__(256)
void norm_silu(float* __restrict__ y)
{
    const size_t i0 = (size_t)blockIdx.x * 256 + threadIdx.x;
    float4* yp = reinterpret_cast<float4*>(y);

    #pragma unroll
    for (int r = 0; r < 2; r++) {
        size_t idx = i0 + (size_t)r * N4HALF;
        int c = (int)((idx >> 14) & 63);
        float sc = g_scale[c];
        float sh = g_shift[c];
        float4 v = yp[idx];
        float t0 = fmaf(v.x, sc, sh);
        float t1 = fmaf(v.y, sc, sh);
        float t2 = fmaf(v.z, sc, sh);
        float t3 = fmaf(v.w, sc, sh);
        v.x = t0 / (1.f + __expf(-t0));
        v.y = t1 / (1.f + __expf(-t1));
        v.z = t2 / (1.f + __expf(-t2));
        v.w = t3 / (1.f + __expf(-t3));
        yp[idx] = v;
    }
}

// ---------------------------------------------------------------------------
extern "C" void kernel_launch(void* const* d_in, const int* in_sizes, int n_in,
                              void* d_out, int out_size)
{
    const float* x      = (const float*)d_in[0];
    const float* w_off  = (const float*)d_in[1];
    const float* b_off  = (const float*)d_in[2];
    const float* w_dcn  = (const float*)d_in[3];
    const float* w_conv = (const float*)d_in[4];
    const float* b_conv = (const float*)d_in[5];
    const float* gamma  = (const float*)d_in[6];
    const float* beta   = (const float*)d_in[7];
    float* out = (float*)d_out;

    cudaFuncSetAttribute(fused_main, cudaFuncAttributeMaxDynamicSharedMemorySize, SMEM_BYTES);

    fused_main<<<NBLK, 256, SMEM_BYTES>>>(x, w_off, b_off, w_dcn, w_conv, b_conv, out);
    stats_kernel<<<COUT, 256>>>(gamma, beta);
    norm_silu<<<N4HALF/256, 256>>>(out);
}